// round 1
// baseline (speedup 1.0000x reference)
#include <cuda_runtime.h>
#include <math.h>

// KMeansClusteringLoss: out = mean_l( min_c ||z_l - mu_c|| )
// z: [L=65536, 1, K=128] fp32, mu: [C=512, K=128] fp32, out: scalar fp32.
//
// d2(l,c) = |z_l|^2 + |mu_c|^2 - 2 <z_l, mu_c>
// Tiled fp32 GEMM (64x64 tile, 4x4 micro-tile) with fused min + mean.

#define KDIM    128
#define MT      64          // points per block
#define CT      64          // centroids per tile
#define SSTRIDE 65          // smem row stride (conflict-free: 65 % 32 == 1)
#define NTHREADS 256

__device__ float g_sum;

__global__ void km_init_kernel() {
    g_sum = 0.0f;
}

__global__ __launch_bounds__(NTHREADS) void km_main_kernel(
    const float* __restrict__ z,
    const float* __restrict__ mu,
    int L, int C)
{
    __shared__ float zs[KDIM * SSTRIDE];   // zs[k*SSTRIDE + m], transposed z tile
    __shared__ float ms[KDIM * SSTRIDE];   // ms[k*SSTRIDE + c], transposed mu tile
    __shared__ float m2s[CT];              // |mu_c|^2 for current tile
    __shared__ float red[MT * 17];         // min-reduction across tx
    __shared__ float rowdist[MT];

    const int tid = threadIdx.x;
    const int tx  = tid & 15;              // 16 columns of threads -> c
    const int ty  = tid >> 4;              // 16 rows of threads    -> m
    const int m0  = blockIdx.x * MT;

    // ---- load z tile, transposed into smem (coalesced global, conflict-free STS)
    for (int idx = tid; idx < MT * KDIM; idx += NTHREADS) {
        int k = idx & (KDIM - 1);
        int m = idx >> 7;                  // idx / 128
        int p = m0 + m;
        zs[k * SSTRIDE + m] = (p < L) ? z[p * KDIM + k] : 0.0f;
    }
    __syncthreads();

    float mincost[4] = {INFINITY, INFINITY, INFINITY, INFINITY};

    for (int c0 = 0; c0 < C; c0 += CT) {
        __syncthreads();   // previous tile's compute done before overwriting ms

        // ---- load mu tile, transposed
        for (int idx = tid; idx < CT * KDIM; idx += NTHREADS) {
            int k = idx & (KDIM - 1);
            int c = idx >> 7;
            int cg = c0 + c;
            ms[k * SSTRIDE + c] = (cg < C) ? mu[cg * KDIM + k] : 0.0f;
        }
        __syncthreads();

        // ---- |mu_c|^2 per centroid in the tile
        if (tid < CT) {
            if (c0 + tid < C) {
                float s = 0.0f;
                #pragma unroll 8
                for (int k = 0; k < KDIM; k++) {
                    float v = ms[k * SSTRIDE + tid];
                    s = fmaf(v, v, s);
                }
                m2s[tid] = s;
            } else {
                m2s[tid] = INFINITY;       // padded centroid never wins the min
            }
        }
        __syncthreads();

        // ---- 64x64 dot products, 4x4 per thread
        float acc[4][4] = {};
        const float* zp = &zs[ty * 4];
        const float* mp = &ms[tx * 4];
        #pragma unroll 4
        for (int k = 0; k < KDIM; k++) {
            float a0 = zp[k * SSTRIDE + 0];
            float a1 = zp[k * SSTRIDE + 1];
            float a2 = zp[k * SSTRIDE + 2];
            float a3 = zp[k * SSTRIDE + 3];
            float b0 = mp[k * SSTRIDE + 0];
            float b1 = mp[k * SSTRIDE + 1];
            float b2 = mp[k * SSTRIDE + 2];
            float b3 = mp[k * SSTRIDE + 3];
            acc[0][0] = fmaf(a0, b0, acc[0][0]);
            acc[0][1] = fmaf(a0, b1, acc[0][1]);
            acc[0][2] = fmaf(a0, b2, acc[0][2]);
            acc[0][3] = fmaf(a0, b3, acc[0][3]);
            acc[1][0] = fmaf(a1, b0, acc[1][0]);
            acc[1][1] = fmaf(a1, b1, acc[1][1]);
            acc[1][2] = fmaf(a1, b2, acc[1][2]);
            acc[1][3] = fmaf(a1, b3, acc[1][3]);
            acc[2][0] = fmaf(a2, b0, acc[2][0]);
            acc[2][1] = fmaf(a2, b1, acc[2][1]);
            acc[2][2] = fmaf(a2, b2, acc[2][2]);
            acc[2][3] = fmaf(a2, b3, acc[2][3]);
            acc[3][0] = fmaf(a3, b0, acc[3][0]);
            acc[3][1] = fmaf(a3, b1, acc[3][1]);
            acc[3][2] = fmaf(a3, b2, acc[3][2]);
            acc[3][3] = fmaf(a3, b3, acc[3][3]);
        }

        // ---- fold into running min of (|mu|^2 - 2*dot)
        #pragma unroll
        for (int j = 0; j < 4; j++) {
            float m2 = m2s[tx * 4 + j];
            #pragma unroll
            for (int i = 0; i < 4; i++) {
                float cost = m2 - 2.0f * acc[i][j];
                mincost[i] = fminf(mincost[i], cost);
            }
        }
    }

    // ---- reduce min across the 16 tx-threads per point row
    #pragma unroll
    for (int i = 0; i < 4; i++)
        red[(ty * 4 + i) * 17 + tx] = mincost[i];
    __syncthreads();

    if (tid < MT) {
        float mn = INFINITY;
        #pragma unroll
        for (int t = 0; t < 16; t++)
            mn = fminf(mn, red[tid * 17 + t]);

        // |z|^2 for this point (conflict-free: lanes vary over tid -> distinct banks)
        float z2 = 0.0f;
        #pragma unroll 8
        for (int k = 0; k < KDIM; k++) {
            float v = zs[k * SSTRIDE + tid];
            z2 = fmaf(v, v, z2);
        }
        float d = sqrtf(fmaxf(z2 + mn, 0.0f));
        if (m0 + tid >= L) d = 0.0f;
        rowdist[tid] = d;
    }
    __syncthreads();

    // ---- block sum of 64 distances -> atomic into global accumulator
    if (tid < 32) {
        float s = rowdist[tid] + rowdist[tid + 32];
        #pragma unroll
        for (int o = 16; o > 0; o >>= 1)
            s += __shfl_down_sync(0xffffffffu, s, o);
        if (tid == 0)
            atomicAdd(&g_sum, s);
    }
}

__global__ void km_final_kernel(float* __restrict__ out, int L) {
    out[0] = g_sum / (float)L;
}

extern "C" void kernel_launch(void* const* d_in, const int* in_sizes, int n_in,
                              void* d_out, int out_size) {
    const float* z  = (const float*)d_in[0];
    const float* mu = (const float*)d_in[1];
    float* out = (float*)d_out;

    int L = in_sizes[0] / KDIM;   // 65536 (middle dim is 1)
    int C = in_sizes[1] / KDIM;   // 512

    km_init_kernel<<<1, 1>>>();
    km_main_kernel<<<(L + MT - 1) / MT, NTHREADS>>>(z, mu, L, C);
    km_final_kernel<<<1, 1>>>(out, L);
}

// round 3
// speedup vs baseline: 7.1336x; 7.1336x over previous
#include <cuda_runtime.h>
#include <cuda_bf16.h>
#include <cstdint>
#include <math.h>

// KMeansClusteringLoss via warp-level bf16 HMMA (mma.sync m16n8k16):
//   cost(l,c) = |mu_c|^2 - 2 <z_l, mu_c>,  d(l) = sqrt(max(|z_l|^2 + min_c cost, 0))
//   out = mean_l d(l)
//
// tcgen05 is unavailable (harness lowers via compute_103, not sm_103a), so we
// use mma.sync with the min fused directly into the accumulator epilogue.
// Persistent kernel: mu tile (512x128 bf16) loaded to SMEM once per CTA,
// reused across all z tiles that CTA processes.

#define KDIM  128
#define CDIM  512
#define MT    128          // z rows per tile
#define NTHREADS 256       // 8 warps; warp w owns rows [16w, 16w+16)

#define STRIDE_B 272       // bytes per row: 128 bf16 (256B) + 16B pad -> LDSM conflict-free

// dynamic smem layout (bytes)
#define SM_MU   0                       // 512 x 272
#define SM_Z    (SM_MU + CDIM * STRIDE_B)       // 128 x 272
#define SM_M2   (SM_Z + MT * STRIDE_B)          // 512 f32
#define SM_Z2   (SM_M2 + CDIM * 4)              // 128 f32
#define SM_RED  (SM_Z2 + MT * 4)                // 8 f32
#define SMEM_BYTES (SM_RED + 32)

__device__ float g_sum;
__device__ unsigned int g_cnt;
__device__ __align__(16) __nv_bfloat16 g_mu_bf[CDIM * KDIM];
__device__ float g_m2[CDIM];

// ---------------- helpers ----------------
__device__ __forceinline__ uint32_t smem_u32(const void* p) {
    uint32_t a;
    asm("{ .reg .u64 t; cvta.to.shared.u64 t, %1; cvt.u32.u64 %0, t; }" : "=r"(a) : "l"(p));
    return a;
}
__device__ __forceinline__ void ldsm_x4(uint32_t& r0, uint32_t& r1, uint32_t& r2, uint32_t& r3,
                                        uint32_t addr) {
    asm volatile("ldmatrix.sync.aligned.m8n8.x4.shared.b16 {%0,%1,%2,%3}, [%4];"
                 : "=r"(r0), "=r"(r1), "=r"(r2), "=r"(r3) : "r"(addr));
}
__device__ __forceinline__ void ldsm_x2(uint32_t& r0, uint32_t& r1, uint32_t addr) {
    asm volatile("ldmatrix.sync.aligned.m8n8.x2.shared.b16 {%0,%1}, [%2];"
                 : "=r"(r0), "=r"(r1) : "r"(addr));
}
__device__ __forceinline__ void mma_bf16(float* d, const uint32_t* a, const uint32_t* b) {
    asm volatile(
        "mma.sync.aligned.m16n8k16.row.col.f32.bf16.bf16.f32 "
        "{%0,%1,%2,%3}, {%4,%5,%6,%7}, {%8,%9}, {%0,%1,%2,%3};"
        : "+f"(d[0]), "+f"(d[1]), "+f"(d[2]), "+f"(d[3])
        : "r"(a[0]), "r"(a[1]), "r"(a[2]), "r"(a[3]), "r"(b[0]), "r"(b[1]));
}

// ---------------- prologue: mu fp32 -> bf16, m2, zero accumulators ----------------
__global__ void km_prep(const float* __restrict__ mu) {
    if (blockIdx.x == 0 && threadIdx.x == 0) { g_sum = 0.0f; g_cnt = 0u; }
    int warp = (blockIdx.x * blockDim.x + threadIdx.x) >> 5;   // 1 warp per centroid
    int lane = threadIdx.x & 31;
    if (warp >= CDIM) return;

    float4 v = reinterpret_cast<const float4*>(mu + warp * KDIM)[lane];
    __nv_bfloat162 p0 = __floats2bfloat162_rn(v.x, v.y);
    __nv_bfloat162 p1 = __floats2bfloat162_rn(v.z, v.w);
    reinterpret_cast<__nv_bfloat162*>(g_mu_bf + warp * KDIM)[lane * 2 + 0] = p0;
    reinterpret_cast<__nv_bfloat162*>(g_mu_bf + warp * KDIM)[lane * 2 + 1] = p1;

    float a0 = __bfloat162float(p0.x), a1 = __bfloat162float(p0.y);
    float a2 = __bfloat162float(p1.x), a3 = __bfloat162float(p1.y);
    float s = a0 * a0 + a1 * a1 + a2 * a2 + a3 * a3;
    #pragma unroll
    for (int o = 16; o > 0; o >>= 1) s += __shfl_down_sync(0xffffffffu, s, o);
    if (lane == 0) g_m2[warp] = s;
}

// ---------------- persistent main kernel ----------------
__global__ void __launch_bounds__(NTHREADS, 1) km_main(
    const float* __restrict__ z, float* __restrict__ out, int L, int ntiles)
{
    extern __shared__ char smem[];
    const uint32_t sbase = smem_u32(smem);
    float* m2s = reinterpret_cast<float*>(smem + SM_M2);
    float* z2s = reinterpret_cast<float*>(smem + SM_Z2);
    float* red = reinterpret_cast<float*>(smem + SM_RED);

    const int tid  = threadIdx.x;
    const int wid  = tid >> 5;
    const int lane = tid & 31;
    const int tg   = lane & 3;          // thread-in-group (col pair)
    const int g    = lane >> 2;         // group (row within m16 half)
    const int r0   = wid * 16;          // warp's first row in tile

    // ---- resident mu tile: 512 x 128 bf16 into padded SMEM rows ----
    for (int idx = tid; idx < CDIM * 16; idx += NTHREADS) {      // 16B chunks, 16/row
        int c = idx >> 4, kc = idx & 15;
        uint4 q = reinterpret_cast<const uint4*>(g_mu_bf)[idx];
        *reinterpret_cast<uint4*>(smem + SM_MU + c * STRIDE_B + kc * 16) = q;
    }
    for (int i = tid; i < CDIM; i += NTHREADS) m2s[i] = g_m2[i];

    for (int tile = blockIdx.x; tile < ntiles; tile += gridDim.x) {
        const size_t m0 = (size_t)tile * MT;

        // ---- load z tile fp32 -> bf16 into padded SMEM (8 floats / thread-iter) ----
        for (int idx = tid; idx < MT * 16; idx += NTHREADS) {
            int row = idx >> 4, kc = idx & 15;
            const float4* p = reinterpret_cast<const float4*>(z + (m0 + row) * KDIM + kc * 8);
            float4 v0 = p[0], v1 = p[1];
            __nv_bfloat162 b0 = __floats2bfloat162_rn(v0.x, v0.y);
            __nv_bfloat162 b1 = __floats2bfloat162_rn(v0.z, v0.w);
            __nv_bfloat162 b2 = __floats2bfloat162_rn(v1.x, v1.y);
            __nv_bfloat162 b3 = __floats2bfloat162_rn(v1.z, v1.w);
            uint4 q;
            q.x = *reinterpret_cast<uint32_t*>(&b0);
            q.y = *reinterpret_cast<uint32_t*>(&b1);
            q.z = *reinterpret_cast<uint32_t*>(&b2);
            q.w = *reinterpret_cast<uint32_t*>(&b3);
            *reinterpret_cast<uint4*>(smem + SM_Z + row * STRIDE_B + kc * 16) = q;
        }
        __syncthreads();

        // ---- |z|^2 per row from the same bf16 values (threads 0..127) ----
        if (tid < MT) {
            float s = 0.0f;
            #pragma unroll
            for (int j = 0; j < 16; j++) {
                uint4 q = *reinterpret_cast<const uint4*>(smem + SM_Z + tid * STRIDE_B + j * 16);
                uint32_t u[4] = {q.x, q.y, q.z, q.w};
                #pragma unroll
                for (int e = 0; e < 4; e++) {
                    float lo = __uint_as_float(u[e] << 16);
                    float hi = __uint_as_float(u[e] & 0xffff0000u);
                    s = fmaf(lo, lo, s);
                    s = fmaf(hi, hi, s);
                }
            }
            z2s[tid] = s;
        }

        // ---- A fragments: 8 k-steps of m16k16 for this warp's 16 rows ----
        uint32_t A[8][4];
        {
            uint32_t abase = sbase + SM_Z + (r0 + (lane & 15)) * STRIDE_B + ((lane & 16) ? 16 : 0);
            #pragma unroll
            for (int kk = 0; kk < 8; kk++)
                ldsm_x4(A[kk][0], A[kk][1], A[kk][2], A[kk][3], abase + kk * 32);
        }

        // ---- main loop: 64 n-tiles (n8), unrolled x2, min fused in epilogue ----
        float mn0 = INFINITY, mn1 = INFINITY;
        uint32_t bbase = sbase + SM_MU + (lane & 7) * STRIDE_B + ((lane & 8) ? 16 : 0);

        #pragma unroll 2
        for (int nt2 = 0; nt2 < 32; nt2++) {
            const int n0 = nt2 * 16;
            float acc0[4] = {0.f, 0.f, 0.f, 0.f};
            float acc1[4] = {0.f, 0.f, 0.f, 0.f};
            uint32_t b0a = bbase + n0 * STRIDE_B;
            uint32_t b1a = b0a + 8 * STRIDE_B;
            #pragma unroll
            for (int kk = 0; kk < 8; kk++) {
                uint32_t b0[2], b1[2];
                ldsm_x2(b0[0], b0[1], b0a + kk * 32);
                ldsm_x2(b1[0], b1[1], b1a + kk * 32);
                mma_bf16(acc0, A[kk], b0);
                mma_bf16(acc1, A[kk], b1);
            }
            float2 ma = *reinterpret_cast<const float2*>(&m2s[n0 + 2 * tg]);
            float2 mb = *reinterpret_cast<const float2*>(&m2s[n0 + 8 + 2 * tg]);
            mn0 = fminf(mn0, fmaf(-2.0f, acc0[0], ma.x));
            mn0 = fminf(mn0, fmaf(-2.0f, acc0[1], ma.y));
            mn1 = fminf(mn1, fmaf(-2.0f, acc0[2], ma.x));
            mn1 = fminf(mn1, fmaf(-2.0f, acc0[3], ma.y));
            mn0 = fminf(mn0, fmaf(-2.0f, acc1[0], mb.x));
            mn0 = fminf(mn0, fmaf(-2.0f, acc1[1], mb.y));
            mn1 = fminf(mn1, fmaf(-2.0f, acc1[2], mb.x));
            mn1 = fminf(mn1, fmaf(-2.0f, acc1[3], mb.y));
        }

        // ---- min across the 4 threads sharing each row ----
        mn0 = fminf(mn0, __shfl_xor_sync(0xffffffffu, mn0, 1));
        mn0 = fminf(mn0, __shfl_xor_sync(0xffffffffu, mn0, 2));
        mn1 = fminf(mn1, __shfl_xor_sync(0xffffffffu, mn1, 1));
        mn1 = fminf(mn1, __shfl_xor_sync(0xffffffffu, mn1, 2));

        __syncthreads();   // z2s writes visible

        float s = 0.0f;
        if (tg == 0) {
            float d0 = sqrtf(fmaxf(z2s[r0 + g] + mn0, 0.0f));
            float d1 = sqrtf(fmaxf(z2s[r0 + 8 + g] + mn1, 0.0f));
            s = d0 + d1;
        }
        #pragma unroll
        for (int o = 16; o > 0; o >>= 1) s += __shfl_down_sync(0xffffffffu, s, o);
        if (lane == 0) red[wid] = s;
        __syncthreads();

        if (tid == 0) {
            float t = red[0] + red[1] + red[2] + red[3]
                    + red[4] + red[5] + red[6] + red[7];
            atomicAdd(&g_sum, t);
            __threadfence();
            unsigned int c = atomicAdd(&g_cnt, 1u);
            if (c == (unsigned int)(ntiles - 1)) {
                out[0] = (*(volatile float*)&g_sum) / (float)L;
            }
        }
        __syncthreads();   // red/z2s safe to reuse next tile
    }
}

extern "C" void kernel_launch(void* const* d_in, const int* in_sizes, int n_in,
                              void* d_out, int out_size) {
    const float* z  = (const float*)d_in[0];
    const float* mu = (const float*)d_in[1];
    float* out = (float*)d_out;

    int L = in_sizes[0] / KDIM;   // 65536
    int ntiles = L / MT;          // 512

    static int nsm = 0;
    if (nsm == 0) {
        cudaDeviceGetAttribute(&nsm, cudaDevAttrMultiProcessorCount, 0);
        cudaFuncSetAttribute(km_main, cudaFuncAttributeMaxDynamicSharedMemorySize, SMEM_BYTES);
    }
    int grid = (ntiles < nsm) ? ntiles : nsm;

    km_prep<<<64, 256>>>(mu);
    km_main<<<grid, NTHREADS, SMEM_BYTES>>>(z, out, L, ntiles);
}